// round 5
// baseline (speedup 1.0000x reference)
#include <cuda_runtime.h>

#define ALPHA 0.1f
#define BETA  0.96f
#define VTHR  2.0f
#define DEPTH 8

__device__ __forceinline__ void snn_step(float xv, float& syn, float& mem,
                                         float& spk_o, float& syn_o, float& mem_o)
{
    bool reset = (mem > VTHR);
    syn = fmaf(ALPHA, syn, xv);
    mem = fmaf(BETA,  mem, syn);
    if (reset) { syn = 0.f; mem = 0.f; }
    spk_o = (mem > VTHR) ? 1.f : 0.f;
    syn_o = syn;
    mem_o = mem;
}

__device__ __forceinline__ void snn_step2(float2 xv,
                                          float& s0, float& s1,
                                          float& m0, float& m1,
                                          float2* __restrict__ spk,
                                          float2* __restrict__ syn,
                                          float2* __restrict__ mem,
                                          size_t row)
{
    float2 sp, so, mo;
    snn_step(xv.x, s0, m0, sp.x, so.x, mo.x);
    snn_step(xv.y, s1, m1, sp.y, so.y, mo.y);
    __stcs(spk + row, sp);
    __stcs(syn + row, so);
    __stcs(mem + row, mo);
}

// One thread owns 2 adjacent channels; scans all T steps with (syn, mem) in
// registers. DEPTH=8 independent prefetch batch keeps 8 LDG.64 in flight per
// thread. 2048 one-warp blocks -> ~13.8 warps/SM (~3.5 per SMSP), covering
// single-warp stalls that previously idled whole sub-partitions.
__global__ __launch_bounds__(32, 16)
void snn_scan_kernel(const float2* __restrict__ x,
                     float2* __restrict__ spk_out,
                     float2* __restrict__ syn_out,
                     float2* __restrict__ mem_out,
                     int T, int BN2)
{
    int idx = blockIdx.x * blockDim.x + threadIdx.x;
    if (idx >= BN2) return;

    float s0 = 0.f, s1 = 0.f;
    float m0 = 0.f, m1 = 0.f;

    const size_t stride = (size_t)BN2;
    const size_t batch_stride = (size_t)DEPTH * stride;

    // prefetch batch t = 0..DEPTH-1
    float2 pf[DEPTH];
    const float2* xp = x + idx;
    #pragma unroll
    for (int i = 0; i < DEPTH; ++i)
        pf[i] = __ldcs(xp + (size_t)i * stride);

    for (int t = 0; t < T; t += DEPTH) {
        // issue next batch's loads first (independent of the recurrence);
        // clamp so the final iteration re-reads valid rows (values unused)
        const float2* xq = (t + DEPTH < T) ? (xp + batch_stride) : xp;
        float2 nx[DEPTH];
        #pragma unroll
        for (int i = 0; i < DEPTH; ++i)
            nx[i] = __ldcs(xq + (size_t)i * stride);

        size_t row = (size_t)t * stride + idx;
        #pragma unroll
        for (int i = 0; i < DEPTH; ++i) {
            snn_step2(pf[i], s0, s1, m0, m1,
                      spk_out, syn_out, mem_out, row);
            row += stride;
        }

        #pragma unroll
        for (int i = 0; i < DEPTH; ++i)
            pf[i] = nx[i];

        xp += batch_stride;
    }
}

extern "C" void kernel_launch(void* const* d_in, const int* in_sizes, int n_in,
                              void* d_out, int out_size)
{
    const float* x = (const float*)d_in[0];
    float* out = (float*)d_out;

    const int T = 512;
    int total = in_sizes[0];          // T * B * N
    int BN = total / T;               // 131072
    int BN2 = BN / 2;                 // 65536 float2 lanes

    float2* spk = (float2*)out;
    float2* syn = (float2*)(out + (size_t)total);
    float2* mem = (float2*)(out + 2 * (size_t)total);

    int threads = 32;
    int blocks = (BN2 + threads - 1) / threads;   // 2048 one-warp blocks
    snn_scan_kernel<<<blocks, threads>>>((const float2*)x, spk, syn, mem, T, BN2);
}